// round 7
// baseline (speedup 1.0000x reference)
#include <cuda_runtime.h>
#include <cuda_bf16.h>
#include <cstdint>

// Problem dims
#define S_ 512
#define B_ 128
#define E_ 100
#define H_ 256
#define T_ 9
#define G_ 1024   // 4*H

// LSTM tiling
#define UPC 32    // units per CTA
#define BT  16    // batches per cluster
#define CLN 8     // CTAs per cluster

// ---------------- scratch (device globals; no allocations) ----------------
__device__ float g_xg[2][S_ * B_ * G_];   // input projections + bias, [dir][s][b][4H]
__device__ float g_hT[2][S_ * H_ * B_];   // hidden states TRANSPOSED [dir][s][unit][batch]
__device__ float g_em[B_ * S_ * T_];      // emissions [b][s][t]

__device__ __forceinline__ float fsig(float x) {
    return __fdividef(1.f, 1.f + __expf(-x));
}
__device__ __forceinline__ float ftanh(float x) {
    return __fdividef(2.f, 1.f + __expf(-2.f * x)) - 1.f;
}

// packed fp32x2 FMA (sm_103a FFMA2)
__device__ __forceinline__ unsigned long long ffma2(unsigned long long a,
                                                    unsigned long long b,
                                                    unsigned long long c) {
    unsigned long long d;
    asm("fma.rn.f32x2 %0, %1, %2, %3;" : "=l"(d) : "l"(a), "l"(b), "l"(c));
    return d;
}
__device__ __forceinline__ float2 unpack2(unsigned long long v) {
    float2 r;
    asm("mov.b64 {%0, %1}, %2;" : "=f"(r.x), "=f"(r.y) : "l"(v));
    return r;
}
union F4U2 { float4 f4; unsigned long long u2[2]; };

__device__ __forceinline__ uint32_t smem_u32(const void* p) {
    uint32_t a;
    asm("{ .reg .u64 t; cvta.to.shared.u64 t, %1; cvt.u32.u64 %0, t; }"
        : "=r"(a) : "l"(p));
    return a;
}
__device__ __forceinline__ uint32_t mapa_rank(uint32_t addr, uint32_t rank) {
    uint32_t r;
    asm("mapa.shared::cluster.u32 %0, %1, %2;" : "=r"(r) : "r"(addr), "r"(rank));
    return r;
}
__device__ __forceinline__ void st_cluster_f32x2(uint32_t addr, float2 v) {
    asm volatile("st.shared::cluster.v2.f32 [%0], {%1, %2};"
                 :: "r"(addr), "f"(v.x), "f"(v.y) : "memory");
}
__device__ __forceinline__ void cluster_sync() {
    asm volatile("barrier.cluster.arrive.aligned;" ::: "memory");
    asm volatile("barrier.cluster.wait.aligned;" ::: "memory");
}

// ---------------- Kernel A: embed gather + input projection --------------
__global__ void xg_kernel(const int* __restrict__ data,
                          const float* __restrict__ emb,
                          const float* __restrict__ Wf,
                          const float* __restrict__ bf,
                          const float* __restrict__ Wb,
                          const float* __restrict__ bb) {
    extern __shared__ float sm[];
    float* Xsm = sm;          // [100][36]
    float* Wsm = sm + 3600;   // [100][132]

    int tt  = blockIdx.x;
    int gt  = blockIdx.y;
    int dir = gt >> 3;
    int g0  = (gt & 7) * 128;
    const float* W    = dir ? Wb : Wf;
    const float* bias = dir ? bb : bf;

    for (int idx = threadIdx.x; idx < 32 * E_; idx += 256) {
        int j = idx / E_, k = idx - j * E_;
        int tok = tt * 32 + j;            // tok = s*128 + b
        int s = tok >> 7, b = tok & 127;
        int row = data[b * S_ + s];
        Xsm[k * 36 + j] = emb[row * E_ + k];
    }
    for (int idx = threadIdx.x; idx < 128 * E_; idx += 256) {
        int r = idx / E_, k = idx - r * E_;
        Wsm[k * 132 + r] = W[(g0 + r) * E_ + k];
    }
    __syncthreads();

    int gg = threadIdx.x & 31;
    int tg = threadIdx.x >> 5;
    float acc[4][4];
#pragma unroll
    for (int i = 0; i < 4; i++)
#pragma unroll
        for (int j = 0; j < 4; j++) acc[i][j] = 0.f;

    const float* wp = &Wsm[gg * 4];
    const float* xp = &Xsm[tg * 4];
    for (int k = 0; k < E_; k++) {
        float4 w = *(const float4*)(wp + k * 132);
        float4 x = *(const float4*)(xp + k * 36);
        acc[0][0] += w.x * x.x; acc[0][1] += w.x * x.y; acc[0][2] += w.x * x.z; acc[0][3] += w.x * x.w;
        acc[1][0] += w.y * x.x; acc[1][1] += w.y * x.y; acc[1][2] += w.y * x.z; acc[1][3] += w.y * x.w;
        acc[2][0] += w.z * x.x; acc[2][1] += w.z * x.y; acc[2][2] += w.z * x.z; acc[2][3] += w.z * x.w;
        acc[3][0] += w.w * x.x; acc[3][1] += w.w * x.y; acc[3][2] += w.w * x.z; acc[3][3] += w.w * x.w;
    }

    float b0v = bias[g0 + gg * 4 + 0];
    float b1v = bias[g0 + gg * 4 + 1];
    float b2v = bias[g0 + gg * 4 + 2];
    float b3v = bias[g0 + gg * 4 + 3];
#pragma unroll
    for (int ti = 0; ti < 4; ti++) {
        int tok = tt * 32 + tg * 4 + ti;
        float4 o = make_float4(acc[0][ti] + b0v, acc[1][ti] + b1v,
                               acc[2][ti] + b2v, acc[3][ti] + b3v);
        *(float4*)&g_xg[dir][tok * G_ + g0 + gg * 4] = o;
    }
}

// ---------------- Kernel B: cluster-persistent bidirectional LSTM --------
// 128 CTAs x 256 threads = 16 clusters of 8. Cluster = one (dir, 16-batch
// tile); CTA = 32-unit slice (W slice 132KB smem-resident).
// Thread = 1 unit x 4 gates x 2 batches, gate-packed FFMA2 over full k=256.
// h exchange per step: direct DSMEM push to all 8 CTAs (double-buffered),
// then ONE cluster barrier. No L2, no fences, no atomics on critical path.
// SMEM floats: Wsm [256][132] @0, Hdup [256][36] @33792, Hstage [2][256][16] @43008.
__global__ void __launch_bounds__(256, 1) __cluster_dims__(CLN, 1, 1)
lstm_kernel(const float* __restrict__ Whhf, const float* __restrict__ Whhb) {
    extern __shared__ float sm[];
    float* Wsm    = sm;            // [256][132]: [k][unit*4 + gate]
    float* Hdup   = sm + 33792;    // [256][36]:  [k][pair*4] = (hA,hA,hB,hB)
    float* Hstage = sm + 43008;    // [2][256][16]: compact [buf][unit][batch]

    int cl    = blockIdx.x >> 3;    // cluster id 0..15
    int rank  = blockIdx.x & 7;     // CTA rank in cluster
    int dir   = cl >> 3;
    int btile = cl & 7;
    int b0    = btile * BT;
    int u0    = rank * UPC;
    const float* Whh = dir ? Whhb : Whhf;

    // stage W slice: rows {gate*256 + u0+unit}, unit<32, gate<4
    for (int idx = threadIdx.x; idx < 128 * 256; idx += 256) {
        int r = idx >> 8, k = idx & 255;
        int unit = r >> 2, gate = r & 3;
        Wsm[k * 132 + unit * 4 + gate] = Whh[(gate * 256 + u0 + unit) * 256 + k];
    }

    int lane = threadIdx.x & 31;
    int w    = threadIdx.x >> 5;
    int un = (lane & 7) + (w & 3) * 8;      // 0..31 local unit
    int bg = (lane >> 3) + (w >> 2) * 4;    // 0..7 batch pairs
    int u  = u0 + un;                       // global unit
    int bA = b0 + bg * 2, bB = bA + 1;
    float cA = 0.f, cB = 0.f, hA = 0.f, hB = 0.f;

    // hoisted DSMEM addresses of Hstage[0][u][2bg] in each cluster CTA
    uint32_t baseAddr = smem_u32(&Hstage[u * 16 + bg * 2]);
    uint32_t rem[CLN];
#pragma unroll
    for (int r = 0; r < CLN; r++) rem[r] = mapa_rank(baseAddr, (uint32_t)r);

    const float* wp  = &Wsm[un * 4];
    const float* hp2 = &Hdup[bg * 4];

    __syncthreads();   // W staged

    for (int ts = 0; ts < S_; ts++) {
        int t = dir ? (S_ - 1 - ts) : ts;

        // prefetch xg for this step (in flight during publish+sync)
        const float* xgA = &g_xg[dir][(t * B_ + bA) * G_];
        const float* xgB = &g_xg[dir][(t * B_ + bB) * G_];
        float xa0 = xgA[0 * 256 + u], xa1 = xgA[1 * 256 + u];
        float xa2 = xgA[2 * 256 + u], xa3 = xgA[3 * 256 + u];
        float xb0 = xgB[0 * 256 + u], xb1 = xgB[1 * 256 + u];
        float xb2 = xgB[2 * 256 + u], xb3 = xgB[3 * 256 + u];

        unsigned long long aifA = 0, agoA = 0, aifB = 0, agoB = 0;

        if (ts > 0) {
            // publish h(ts-1) to all 8 CTAs' Hstage[(ts-1)&1]
            uint32_t boff = (uint32_t)(((ts - 1) & 1) * 16384);  // bytes
            float2 hv = make_float2(hA, hB);
#pragma unroll
            for (int r = 0; r < CLN; r++)
                st_cluster_f32x2(rem[r] + boff, hv);

            cluster_sync();   // h(ts-1) visible everywhere; also a CTA barrier

            // re-dup compact Hstage -> Hdup (hA,hA,hB,hB per pair)
            int buf = (ts - 1) & 1;
            const float* src = &Hstage[buf * 4096];
            for (int idx = threadIdx.x; idx < 2048; idx += 256) {
                int k = idx >> 3, p = idx & 7;
                float2 x = *(const float2*)&src[k * 16 + p * 2];
                *(float4*)&Hdup[k * 36 + p * 4] = make_float4(x.x, x.x, x.y, x.y);
            }
            __syncthreads();

#pragma unroll 8
            for (int k = 0; k < H_; k++) {
                F4U2 wv; wv.f4 = *(const float4*)(wp  + k * 132);  // (wi,wf,wg,wo)
                F4U2 hd; hd.f4 = *(const float4*)(hp2 + k * 36);   // (hA,hA,hB,hB)
                aifA = ffma2(wv.u2[0], hd.u2[0], aifA);
                agoA = ffma2(wv.u2[1], hd.u2[0], agoA);
                aifB = ffma2(wv.u2[0], hd.u2[1], aifB);
                agoB = ffma2(wv.u2[1], hd.u2[1], agoB);
            }
        }

        float2 vifA = unpack2(aifA), vgoA = unpack2(agoA);
        float2 vifB = unpack2(aifB), vgoB = unpack2(agoB);

        float aiA = vifA.x + xa0, afA = vifA.y + xa1;
        float agA = vgoA.x + xa2, aoA = vgoA.y + xa3;
        cA = fsig(afA) * cA + fsig(aiA) * ftanh(agA);
        hA = fsig(aoA) * ftanh(cA);

        float aiB = vifB.x + xb0, afB = vifB.y + xb1;
        float agB = vgoB.x + xb2, aoB = vgoB.y + xb3;
        cB = fsig(afB) * cB + fsig(aiB) * ftanh(agB);
        hB = fsig(aoB) * ftanh(cB);

        // gmem store for downstream kernels (off critical path)
        *(float2*)&g_hT[dir][(t * H_ + u) * B_ + bA] = make_float2(hA, hB);
    }
}

// ---------------- Kernel C: MLP emissions (transposed h layout) ----------
__global__ void mlp_kernel(const float* __restrict__ mlpW,
                           const float* __restrict__ mlpb) {
    __shared__ float Wsm[T_ * 2 * H_];
    for (int i = threadIdx.x; i < T_ * 2 * H_; i += 128) Wsm[i] = mlpW[i];
    __syncthreads();

    int s = blockIdx.x;
    int b = threadIdx.x;

    float acc[T_];
#pragma unroll
    for (int t = 0; t < T_; t++) acc[t] = 0.f;

    const float* hf = &g_hT[0][(s * H_) * B_ + b];
    const float* hb = &g_hT[1][(s * H_) * B_ + b];
#pragma unroll 4
    for (int k = 0; k < H_; k++) {
        float v1 = hf[k * B_];
        float v2 = hb[k * B_];
#pragma unroll
        for (int t = 0; t < T_; t++) {
            acc[t] += v1 * Wsm[t * 512 + k];
            acc[t] += v2 * Wsm[t * 512 + 256 + k];
        }
    }
#pragma unroll
    for (int t = 0; t < T_; t++)
        g_em[(b * S_ + s) * T_ + t] = acc[t] + mlpb[t];
}

// ---------------- Kernel D: CRF Viterbi (one warp per batch) -------------
__global__ void viterbi_kernel(const int* __restrict__ data,
                               const float* __restrict__ stt,
                               const float* __restrict__ trn,
                               const float* __restrict__ ett,
                               float* __restrict__ out) {
    __shared__ int sbp[2][S_][10];
    int w = threadIdx.x >> 5, lane = threadIdx.x & 31;
    int b = blockIdx.x * 2 + w;
    int cc = lane < T_ ? lane : (T_ - 1);

    int cnt = 0;
    for (int s = lane; s < S_; s += 32) cnt += (data[b * S_ + s] != 0);
    for (int off = 16; off; off >>= 1) cnt += __shfl_xor_sync(0xFFFFFFFFu, cnt, off);
    int len = cnt;

    float tr[T_];
#pragma unroll
    for (int p = 0; p < T_; p++) tr[p] = trn[p * T_ + cc];

    float score = stt[cc] + g_em[(b * S_ + 0) * T_ + cc];

    for (int t = 1; t < S_; t++) {
        float e = g_em[(b * S_ + t) * T_ + cc];
        float best = -1e30f; int bp = 0;
#pragma unroll
        for (int p = 0; p < T_; p++) {
            float sp = __shfl_sync(0xFFFFFFFFu, score, p);
            float cand = sp + tr[p] + e;
            if (cand > best) { best = cand; bp = p; }   // first-max tie-break
        }
        if (lane < T_) sbp[w][t][lane] = bp;
        if (t < len) score = best;
    }

    float fin = score + ett[cc];
    float bestf = -1e30f; int tag = 0;
#pragma unroll
    for (int p = 0; p < T_; p++) {
        float v = __shfl_sync(0xFFFFFFFFu, fin, p);
        if (v > bestf) { bestf = v; tag = p; }
    }
    if (lane == 0) out[B_ * S_ + b] = bestf;

    if (lane == 0) out[b * S_ + (S_ - 1)] = ((S_ - 1) < len) ? (float)tag : 0.f;
    for (int s2 = S_ - 2; s2 >= 0; s2--) {
        int bpv = sbp[w][s2 + 1][cc];
        int prev = __shfl_sync(0xFFFFFFFFu, bpv, tag);
        if (s2 + 1 < len) tag = prev;
        if (lane == 0) out[b * S_ + s2] = (s2 < len) ? (float)tag : 0.f;
    }
}

// ---------------- launch ----------------
extern "C" void kernel_launch(void* const* d_in, const int* in_sizes, int n_in,
                              void* d_out, int out_size) {
    const int*   data = (const int*)d_in[0];
    // d_in[1] = mask (ignored; mask == (data != 0))
    const float* emb  = (const float*)d_in[2];
    const float* Wihf = (const float*)d_in[3];
    const float* Whhf = (const float*)d_in[4];
    const float* bf   = (const float*)d_in[5];
    const float* Wihb = (const float*)d_in[6];
    const float* Whhb = (const float*)d_in[7];
    const float* bb   = (const float*)d_in[8];
    const float* mlpW = (const float*)d_in[9];
    const float* mlpb = (const float*)d_in[10];
    const float* stt  = (const float*)d_in[11];
    const float* trn  = (const float*)d_in[12];
    const float* ett  = (const float*)d_in[13];
    float* out = (float*)d_out;

    cudaFuncSetAttribute(xg_kernel,   cudaFuncAttributeMaxDynamicSharedMemorySize, 67200);
    cudaFuncSetAttribute(lstm_kernel, cudaFuncAttributeMaxDynamicSharedMemorySize, 204800);

    dim3 gA(2048, 16);
    xg_kernel<<<gA, 256, 67200>>>(data, emb, Wihf, bf, Wihb, bb);
    lstm_kernel<<<128, 256, 204800>>>(Whhf, Whhb);
    mlp_kernel<<<512, 128>>>(mlpW, mlpb);
    viterbi_kernel<<<64, 64>>>(data, stt, trn, ett, out);
}